// round 9
// baseline (speedup 1.0000x reference)
#include <cuda_runtime.h>
#include <cuda_bf16.h>
#include <cuda_fp16.h>
#include <cstdint>

// ---------------------------------------------------------------------------
// Problem constants
// ---------------------------------------------------------------------------
#define B_    32
#define C_    128
#define CIN_  64
#define COUT_ 128
#define H_    128
#define W_    128
#define HW_   (H_ * W_)
#define NCHUNK 9             // one K=64 chunk per 3x3 tap, fp16 single-pass

// ---------------------------------------------------------------------------
// Device scratch (static allocations only)
// ---------------------------------------------------------------------------
__device__ float    g_chsum[B_ * C_];
__device__ int      g_idx[B_ * CIN_];
// Xf16[b][y][x][ci] fp16, 64 ci = 128B per pixel (67 MB)
__device__ __align__(128) __half g_Xf16[(size_t)B_ * H_ * W_ * CIN_];
// Wf16: 9 chunks x [128 couts x 64 k] fp16 linear (147 KB)
__device__ __align__(128) __half g_Wf16[NCHUNK * COUT_ * 64];

// ---------------------------------------------------------------------------
// Helpers
// ---------------------------------------------------------------------------
__device__ __forceinline__ uint32_t smem_u32(const void* p) {
    uint32_t a;
    asm("{ .reg .u64 t; cvta.to.shared.u64 t, %1; cvt.u32.u64 %0, t; }" : "=r"(a) : "l"(p));
    return a;
}

__device__ __forceinline__ void ldsm_x4(uint32_t& r0, uint32_t& r1,
                                        uint32_t& r2, uint32_t& r3, uint32_t addr) {
    asm volatile("ldmatrix.sync.aligned.m8n8.x4.shared.b16 {%0,%1,%2,%3}, [%4];"
                 : "=r"(r0), "=r"(r1), "=r"(r2), "=r"(r3) : "r"(addr));
}

__device__ __forceinline__ void mma16816(float* d, uint32_t a0, uint32_t a1,
                                         uint32_t a2, uint32_t a3,
                                         uint32_t b0, uint32_t b1) {
    asm volatile(
        "mma.sync.aligned.m16n8k16.row.col.f32.f16.f16.f32 "
        "{%0,%1,%2,%3}, {%4,%5,%6,%7}, {%8,%9}, {%0,%1,%2,%3};"
        : "+f"(d[0]), "+f"(d[1]), "+f"(d[2]), "+f"(d[3])
        : "r"(a0), "r"(a1), "r"(a2), "r"(a3), "r"(b0), "r"(b1));
}

// ---------------------------------------------------------------------------
// Kernel 1: per-channel sums
// ---------------------------------------------------------------------------
__global__ __launch_bounds__(256) void chsum_kernel(const float* __restrict__ x) {
    const int ch = blockIdx.x;
    const float4* p = reinterpret_cast<const float4*>(x) + (size_t)ch * (HW_ / 4);
    float s = 0.f;
    for (int i = threadIdx.x; i < HW_ / 4; i += 256) {
        float4 v = p[i];
        s += (v.x + v.y) + (v.z + v.w);
    }
    #pragma unroll
    for (int o = 16; o; o >>= 1) s += __shfl_down_sync(0xffffffffu, s, o);
    __shared__ float red[8];
    if ((threadIdx.x & 31) == 0) red[threadIdx.x >> 5] = s;
    __syncthreads();
    if (threadIdx.x < 8) {
        s = red[threadIdx.x];
        #pragma unroll
        for (int o = 4; o; o >>= 1) s += __shfl_down_sync(0xffu, s, o);
        if (threadIdx.x == 0) g_chsum[ch] = s;
    }
}

// ---------------------------------------------------------------------------
// Kernel 2: select (blocks 0..31) + weight fp16 reorder (blocks 32..)
// ---------------------------------------------------------------------------
__global__ __launch_bounds__(256) void select_wprep_kernel(const float* __restrict__ w) {
    if (blockIdx.x < B_) {
        if (threadIdx.x >= C_) return;
        const int b = blockIdx.x, c = threadIdx.x;
        __shared__ float s[C_];
        s[c] = g_chsum[b * C_ + c];
        __syncthreads();
        const float mine = s[c];
        int rank = 0;
        #pragma unroll 8
        for (int j = 0; j < C_; j++) {
            float v = s[j];
            rank += (v < mine) || (v == mine && j < c);
        }
        if (rank < CIN_) g_idx[b * CIN_ + rank] = c;
    } else {
        int t = (blockIdx.x - B_) * 256 + threadIdx.x;
        if (t >= NCHUNK * COUT_ * 64) return;
        int tap = t >> 13;               // /8192
        int r = (t >> 6) & 127;          // cout
        int k = t & 63;                  // ci
        g_Wf16[t] = __float2half_rn(w[r * (CIN_ * 9) + k * 9 + tap]);
    }
}

// ---------------------------------------------------------------------------
// Kernel 3: gather selected channels, CHW->HWC transpose, fp16 convert
// ---------------------------------------------------------------------------
__global__ __launch_bounds__(256) void gather_split_kernel(const float* __restrict__ x) {
    const int y = blockIdx.x, b = blockIdx.y;
    const int tid = threadIdx.x;
    __shared__ float sv[CIN_][W_ + 1];

    for (int i = tid; i < CIN_ * W_; i += 256) {
        int ci = i >> 7, xx = i & 127;
        int src_c = g_idx[b * CIN_ + ci];
        sv[ci][xx] = x[(((size_t)b * C_ + src_c) * H_ + y) * W_ + xx];
    }
    __syncthreads();

    uint32_t* dst = reinterpret_cast<uint32_t*>(
        g_Xf16 + ((size_t)(b * H_ + y)) * W_ * CIN_);
    for (int o = tid; o < W_ * (CIN_ / 2); o += 256) {
        int xx = o >> 5, cw = o & 31;
        __half h0 = __float2half_rn(sv[2 * cw][xx]);
        __half h1 = __float2half_rn(sv[2 * cw + 1][xx]);
        uint32_t w0 = (uint32_t)*reinterpret_cast<unsigned short*>(&h0) |
                      ((uint32_t)*reinterpret_cast<unsigned short*>(&h1) << 16);
        dst[o] = w0;
    }
}

// ---------------------------------------------------------------------------
// Kernel 4: conv implicit GEMM, mma.sync fp16, ldmatrix fragment loads.
//   CTA = (batch b, 1 output row). M=128 pixels, N=128 couts. 8 warps m32n64.
//   9 chunks (one per tap). A staged per ky (3 stages, 2 bufs); B 3-buf ring
//   with cp.async prefetch depth 2 (wait_group 2). Direct-STG epilogue.
// SMEM (82432B): A0[16640] A1[16640] B0..B2[16384].
// ---------------------------------------------------------------------------
#define A_STAGE_BYTES 16640       // 130 rows x 128B
#define SMEM_TOTAL (2 * A_STAGE_BYTES + 3 * 16384)

extern __shared__ char dynsmem[];

__global__ __launch_bounds__(256, 2) void conv_mma_kernel(
    const float* __restrict__ bias, float* __restrict__ out)
{
    const int y = blockIdx.x;                 // 0..127 output row
    const int b = blockIdx.y;                 // 0..31
    const int tid = threadIdx.x;
    const int wid = tid >> 5;
    const int lane = tid & 31;
    const int g = lane >> 2;                  // 0..7
    const int t4 = lane & 3;                  // 0..3
    const int wm = wid & 3;                   // m tile 0..3 (rows of 32)
    const int wn = wid >> 2;                  // n tile 0..1 (cols of 64)

    char* Abuf[2] = { dynsmem, dynsmem + A_STAGE_BYTES };
    char* Bbuf[3] = { dynsmem + 2 * A_STAGE_BYTES,
                      dynsmem + 2 * A_STAGE_BYTES + 16384,
                      dynsmem + 2 * A_STAGE_BYTES + 32768 };

    __shared__ float sbias[COUT_];
    if (tid < COUT_) sbias[tid] = bias[tid];

    // ldmatrix lane geometry
    const int laneA = lane & 15;              // row-in-16 for A matrices
    const int unitA_half = lane >> 4;         // +0/+1 16B unit
    const int laneB = (lane & 7) + ((lane >> 4) << 3);  // row-in-16 for B
    const int unitB_half = (lane >> 3) & 1;

    float acc[2][8][4];
    #pragma unroll
    for (int mt = 0; mt < 2; mt++)
        #pragma unroll
        for (int nt = 0; nt < 8; nt++)
            #pragma unroll
            for (int r = 0; r < 4; r++) acc[mt][nt][r] = 0.f;

    // ---- A stage prefetch: tile row r -> pixel xx=r-1, input row yy=y+ky-1
    auto prefetchA = [&](int s, int buf) {
        const uint32_t abase = smem_u32(Abuf[buf]);
        const int yy = y + s - 1;
        const bool rowok = ((unsigned)yy < (unsigned)H_);
        #pragma unroll
        for (int it = 0; it < 5; it++) {
            int i = tid + it * 256;
            if (i < 130 * 8) {
                int r = i >> 3, j = i & 7;
                int xx = r - 1;
                bool valid = rowok && ((unsigned)xx < (unsigned)W_);
                int yc = valid ? yy : 0, xc = valid ? xx : 0;
                const char* src = reinterpret_cast<const char*>(
                    g_Xf16 + (((size_t)(b * H_ + yc) * W_ + xc) * CIN_)) + j * 16;
                uint32_t dst = abase + (uint32_t)r * 128u +
                               (uint32_t)((j * 16) ^ ((r & 7) << 4));
                uint32_t sz = valid ? 16u : 0u;
                asm volatile("cp.async.cg.shared.global [%0], [%1], 16, %2;"
                             :: "r"(dst), "l"(src), "r"(sz));
            }
        }
    };

    // ---- B chunk prefetch: 16KB
    auto prefetchB = [&](int t, int buf) {
        const char* wsrc = reinterpret_cast<const char*>(g_Wf16) + (size_t)t * 16384;
        const uint32_t bbase = smem_u32(Bbuf[buf]);
        #pragma unroll
        for (int it = 0; it < 4; it++) {
            int i = tid + it * 256;
            int r = i >> 3, j = i & 7;
            uint32_t dst = bbase + (uint32_t)r * 128u +
                           (uint32_t)((j * 16) ^ ((r & 7) << 4));
            asm volatile("cp.async.cg.shared.global [%0], [%1], 16, 16;"
                         :: "r"(dst), "l"(wsrc + (size_t)r * 128 + j * 16));
        }
    };

    // Pre-loop: group0 = A stage0 + B chunk0; group1 = B chunk1 (+ A stage1)
    prefetchA(0, 0);
    prefetchB(0, 0);
    asm volatile("cp.async.commit_group;" ::: "memory");
    prefetchB(1, 1);
    asm volatile("cp.async.commit_group;" ::: "memory");

    for (int t = 0; t < NCHUNK; t++) {
        const int s = t / 3;                  // ky stage
        const int kx = t - s * 3;
        const int pf = t + 2;                 // depth-2 prefetch target
        if (pf < NCHUNK) {
            // B buffer (pf)%3 was consumed at chunk t-1 (previous barrier).
            prefetchB(pf, pf % 3);
            // A stage for chunk pf: buffer alternates; prior user was stage-2
            // ago, consumed 3+ chunks back.
            if (pf % 3 == 0) prefetchA(pf / 3, (pf / 3) & 1);
        }
        asm volatile("cp.async.commit_group;" ::: "memory");
        asm volatile("cp.async.wait_group 2;" ::: "memory");
        __syncthreads();

        const uint32_t Ab = smem_u32(Abuf[s & 1]);
        const uint32_t Bb = smem_u32(Bbuf[t % 3]);

        // Per-thread fixed row components
        const int rowB0 = wn * 64 + laneB;                 // + nt2*16
        const int rowA0 = wm * 32 + laneA + kx;            // + mt*16

        #pragma unroll
        for (int ks = 0; ks < 4; ks++) {
            uint32_t bf[8][2];
            #pragma unroll
            for (int nt2 = 0; nt2 < 4; nt2++) {
                int row = rowB0 + nt2 * 16;
                uint32_t addr = Bb + (uint32_t)(row << 7) +
                    (uint32_t)((((ks * 2 + unitB_half) << 4)) ^ ((row & 7) << 4));
                ldsm_x4(bf[2 * nt2][0], bf[2 * nt2][1],
                        bf[2 * nt2 + 1][0], bf[2 * nt2 + 1][1], addr);
            }
            #pragma unroll
            for (int mt = 0; mt < 2; mt++) {
                int row = rowA0 + mt * 16;
                uint32_t addr = Ab + (uint32_t)(row << 7) +
                    (uint32_t)((((ks * 2 + unitA_half) << 4)) ^ ((row & 7) << 4));
                uint32_t a0, a1, a2, a3;
                ldsm_x4(a0, a1, a2, a3, addr);
                #pragma unroll
                for (int nt = 0; nt < 8; nt++)
                    mma16816(acc[mt][nt], a0, a1, a2, a3, bf[nt][0], bf[nt][1]);
            }
        }
        __syncthreads();   // chunk consumed; next iter may overwrite buffers
    }

    // ---- epilogue: direct STG.32 stores (each 8-lane g-group = 32B sector) ----
    // Thread owns D rows (pixel) p0=wm*32+mt*16+g (+8), cols n0=wn*64+nt*8+2*t4 (+1).
    #pragma unroll
    for (int mt = 0; mt < 2; mt++) {
        const int p0 = wm * 32 + mt * 16 + g;
        #pragma unroll
        for (int nt = 0; nt < 8; nt++) {
            const int n0 = wn * 64 + nt * 8 + 2 * t4;
            const float bv0 = sbias[n0];
            const float bv1 = sbias[n0 + 1];
            float* o0 = out + (((size_t)b * COUT_ + n0) * H_ + y) * W_;
            float* o1 = o0 + (size_t)HW_;     // n0+1
            o0[p0]     = acc[mt][nt][0] + bv0;
            o1[p0]     = acc[mt][nt][1] + bv1;
            o0[p0 + 8] = acc[mt][nt][2] + bv0;
            o1[p0 + 8] = acc[mt][nt][3] + bv1;
        }
    }
}

// ---------------------------------------------------------------------------
extern "C" void kernel_launch(void* const* d_in, const int* in_sizes, int n_in,
                              void* d_out, int out_size) {
    const float* x  = (const float*)d_in[0];   // [32,128,128,128]
    const float* w  = (const float*)d_in[1];   // [128,64,3,3]
    const float* bv = (const float*)d_in[2];   // [128]
    float* out = (float*)d_out;

    static bool attr_set = false;
    if (!attr_set) {
        cudaFuncSetAttribute(conv_mma_kernel,
                             cudaFuncAttributeMaxDynamicSharedMemorySize, SMEM_TOTAL);
        attr_set = true;
    }

    chsum_kernel<<<B_ * C_, 256>>>(x);
    select_wprep_kernel<<<B_ + (NCHUNK * COUT_ * 64 + 255) / 256, 256>>>(w);
    gather_split_kernel<<<dim3(H_, B_), 256>>>(x);
    conv_mma_kernel<<<dim3(H_, B_), 256, SMEM_TOTAL>>>(bv, out);
}

// round 10
// speedup vs baseline: 1.0233x; 1.0233x over previous
#include <cuda_runtime.h>
#include <cuda_bf16.h>
#include <cuda_fp16.h>
#include <cstdint>

// ---------------------------------------------------------------------------
// Problem constants
// ---------------------------------------------------------------------------
#define B_    32
#define C_    128
#define CIN_  64
#define COUT_ 128
#define H_    128
#define W_    128
#define HW_   (H_ * W_)
#define NCHUNK 9             // one K=64 chunk per 3x3 tap, fp16 single-pass

// ---------------------------------------------------------------------------
// Device scratch (static allocations only)
// ---------------------------------------------------------------------------
__device__ float    g_chsum[B_ * C_];
__device__ int      g_idx[B_ * CIN_];
// Xf16[b][y][x][ci] fp16, 64 ci = 128B per pixel (67 MB)
__device__ __align__(128) __half g_Xf16[(size_t)B_ * H_ * W_ * CIN_];
// Wf16: 9 chunks x [128 couts x 64 k] fp16 linear (147 KB)
__device__ __align__(128) __half g_Wf16[NCHUNK * COUT_ * 64];

// ---------------------------------------------------------------------------
// Helpers
// ---------------------------------------------------------------------------
__device__ __forceinline__ uint32_t smem_u32(const void* p) {
    uint32_t a;
    asm("{ .reg .u64 t; cvta.to.shared.u64 t, %1; cvt.u32.u64 %0, t; }" : "=r"(a) : "l"(p));
    return a;
}

__device__ __forceinline__ void ldsm_x4(uint32_t& r0, uint32_t& r1,
                                        uint32_t& r2, uint32_t& r3, uint32_t addr) {
    asm volatile("ldmatrix.sync.aligned.m8n8.x4.shared.b16 {%0,%1,%2,%3}, [%4];"
                 : "=r"(r0), "=r"(r1), "=r"(r2), "=r"(r3) : "r"(addr));
}

__device__ __forceinline__ void mma16816(float* d, uint32_t a0, uint32_t a1,
                                         uint32_t a2, uint32_t a3,
                                         uint32_t b0, uint32_t b1) {
    asm volatile(
        "mma.sync.aligned.m16n8k16.row.col.f32.f16.f16.f32 "
        "{%0,%1,%2,%3}, {%4,%5,%6,%7}, {%8,%9}, {%0,%1,%2,%3};"
        : "+f"(d[0]), "+f"(d[1]), "+f"(d[2]), "+f"(d[3])
        : "r"(a0), "r"(a1), "r"(a2), "r"(a3), "r"(b0), "r"(b1));
}

// ---------------------------------------------------------------------------
// Kernel 1: per-channel sums
// ---------------------------------------------------------------------------
__global__ __launch_bounds__(256) void chsum_kernel(const float* __restrict__ x) {
    const int ch = blockIdx.x;
    const float4* p = reinterpret_cast<const float4*>(x) + (size_t)ch * (HW_ / 4);
    float s = 0.f;
    for (int i = threadIdx.x; i < HW_ / 4; i += 256) {
        float4 v = p[i];
        s += (v.x + v.y) + (v.z + v.w);
    }
    #pragma unroll
    for (int o = 16; o; o >>= 1) s += __shfl_down_sync(0xffffffffu, s, o);
    __shared__ float red[8];
    if ((threadIdx.x & 31) == 0) red[threadIdx.x >> 5] = s;
    __syncthreads();
    if (threadIdx.x < 8) {
        s = red[threadIdx.x];
        #pragma unroll
        for (int o = 4; o; o >>= 1) s += __shfl_down_sync(0xffu, s, o);
        if (threadIdx.x == 0) g_chsum[ch] = s;
    }
}

// ---------------------------------------------------------------------------
// Kernel 2: select (blocks 0..31) + weight fp16 reorder (blocks 32..)
// ---------------------------------------------------------------------------
__global__ __launch_bounds__(256) void select_wprep_kernel(const float* __restrict__ w) {
    if (blockIdx.x < B_) {
        if (threadIdx.x >= C_) return;
        const int b = blockIdx.x, c = threadIdx.x;
        __shared__ float s[C_];
        s[c] = g_chsum[b * C_ + c];
        __syncthreads();
        const float mine = s[c];
        int rank = 0;
        #pragma unroll 8
        for (int j = 0; j < C_; j++) {
            float v = s[j];
            rank += (v < mine) || (v == mine && j < c);
        }
        if (rank < CIN_) g_idx[b * CIN_ + rank] = c;
    } else {
        int t = (blockIdx.x - B_) * 256 + threadIdx.x;
        if (t >= NCHUNK * COUT_ * 64) return;
        int tap = t >> 13;               // /8192
        int r = (t >> 6) & 127;          // cout
        int k = t & 63;                  // ci
        g_Wf16[t] = __float2half_rn(w[r * (CIN_ * 9) + k * 9 + tap]);
    }
}

// ---------------------------------------------------------------------------
// Kernel 3: gather selected channels, CHW->HWC transpose, fp16 convert
// ---------------------------------------------------------------------------
__global__ __launch_bounds__(256) void gather_split_kernel(const float* __restrict__ x) {
    const int y = blockIdx.x, b = blockIdx.y;
    const int tid = threadIdx.x;
    __shared__ float sv[CIN_][W_ + 1];

    for (int i = tid; i < CIN_ * W_; i += 256) {
        int ci = i >> 7, xx = i & 127;
        int src_c = g_idx[b * CIN_ + ci];
        sv[ci][xx] = x[(((size_t)b * C_ + src_c) * H_ + y) * W_ + xx];
    }
    __syncthreads();

    uint32_t* dst = reinterpret_cast<uint32_t*>(
        g_Xf16 + ((size_t)(b * H_ + y)) * W_ * CIN_);
    for (int o = tid; o < W_ * (CIN_ / 2); o += 256) {
        int xx = o >> 5, cw = o & 31;
        __half h0 = __float2half_rn(sv[2 * cw][xx]);
        __half h1 = __float2half_rn(sv[2 * cw + 1][xx]);
        uint32_t w0 = (uint32_t)*reinterpret_cast<unsigned short*>(&h0) |
                      ((uint32_t)*reinterpret_cast<unsigned short*>(&h1) << 16);
        dst[o] = w0;
    }
}

// ---------------------------------------------------------------------------
// Kernel 4: conv implicit GEMM, mma.sync fp16, ldmatrix fragment loads.
//   CTA = (batch b, 1 output row). M=128 pixels, N=128 couts. 8 warps m32n64.
//   9 chunks. ONE __syncthreads per chunk (commit-after-wait ordering).
//   B fragments register-double-buffered across ks (load ks+1 during HMMA ks).
// SMEM (82432B): A0[16640] A1[16640] B0..B2[16384]. Direct-STG epilogue.
// ---------------------------------------------------------------------------
#define A_STAGE_BYTES 16640       // 130 rows x 128B
#define SMEM_TOTAL (2 * A_STAGE_BYTES + 3 * 16384)

extern __shared__ char dynsmem[];

__global__ __launch_bounds__(256, 2) void conv_mma_kernel(
    const float* __restrict__ bias, float* __restrict__ out)
{
    const int y = blockIdx.x;                 // 0..127 output row
    const int b = blockIdx.y;                 // 0..31
    const int tid = threadIdx.x;
    const int wid = tid >> 5;
    const int lane = tid & 31;
    const int g = lane >> 2;                  // 0..7
    const int t4 = lane & 3;                  // 0..3
    const int wm = wid & 3;                   // m tile 0..3 (rows of 32)
    const int wn = wid >> 2;                  // n tile 0..1 (cols of 64)

    char* Abuf[2] = { dynsmem, dynsmem + A_STAGE_BYTES };
    char* Bbuf[3] = { dynsmem + 2 * A_STAGE_BYTES,
                      dynsmem + 2 * A_STAGE_BYTES + 16384,
                      dynsmem + 2 * A_STAGE_BYTES + 32768 };

    __shared__ float sbias[COUT_];
    if (tid < COUT_) sbias[tid] = bias[tid];

    // ldmatrix lane geometry
    const int laneA = lane & 15;              // row-in-16 for A matrices
    const int unitA_half = lane >> 4;         // +0/+1 16B unit
    const int laneB = (lane & 7) + ((lane >> 4) << 3);  // row-in-16 for B
    const int unitB_half = (lane >> 3) & 1;

    float acc[2][8][4];
    #pragma unroll
    for (int mt = 0; mt < 2; mt++)
        #pragma unroll
        for (int nt = 0; nt < 8; nt++)
            #pragma unroll
            for (int r = 0; r < 4; r++) acc[mt][nt][r] = 0.f;

    // ---- A stage prefetch: tile row r -> pixel xx=r-1, input row yy=y+ky-1
    auto prefetchA = [&](int s, int buf) {
        const uint32_t abase = smem_u32(Abuf[buf]);
        const int yy = y + s - 1;
        const bool rowok = ((unsigned)yy < (unsigned)H_);
        #pragma unroll
        for (int it = 0; it < 5; it++) {
            int i = tid + it * 256;
            if (i < 130 * 8) {
                int r = i >> 3, j = i & 7;
                int xx = r - 1;
                bool valid = rowok && ((unsigned)xx < (unsigned)W_);
                int yc = valid ? yy : 0, xc = valid ? xx : 0;
                const char* src = reinterpret_cast<const char*>(
                    g_Xf16 + (((size_t)(b * H_ + yc) * W_ + xc) * CIN_)) + j * 16;
                uint32_t dst = abase + (uint32_t)r * 128u +
                               (uint32_t)((j * 16) ^ ((r & 7) << 4));
                uint32_t sz = valid ? 16u : 0u;
                asm volatile("cp.async.cg.shared.global [%0], [%1], 16, %2;"
                             :: "r"(dst), "l"(src), "r"(sz));
            }
        }
    };

    // ---- B chunk prefetch: 16KB
    auto prefetchB = [&](int t, int buf) {
        const char* wsrc = reinterpret_cast<const char*>(g_Wf16) + (size_t)t * 16384;
        const uint32_t bbase = smem_u32(Bbuf[buf]);
        #pragma unroll
        for (int it = 0; it < 4; it++) {
            int i = tid + it * 256;
            int r = i >> 3, j = i & 7;
            uint32_t dst = bbase + (uint32_t)r * 128u +
                           (uint32_t)((j * 16) ^ ((r & 7) << 4));
            asm volatile("cp.async.cg.shared.global [%0], [%1], 16, 16;"
                         :: "r"(dst), "l"(wsrc + (size_t)r * 128 + j * 16));
        }
    };

    // Pre-loop: G0 = A stage0 + B chunk0; G1 = B chunk1
    prefetchA(0, 0);
    prefetchB(0, 0);
    asm volatile("cp.async.commit_group;" ::: "memory");
    prefetchB(1, 1);
    asm volatile("cp.async.commit_group;" ::: "memory");

    for (int t = 0; t < NCHUNK; t++) {
        const int s = t / 3;                  // ky stage
        const int kx = t - s * 3;

        // wait for group t (allow group t+1 pending), then ONE barrier
        asm volatile("cp.async.wait_group 1;" ::: "memory");
        __syncthreads();

        // prefetch chunk t+2 (buffer (t+2)%3 == (t-1)%3: consumers done at
        // t-1, covered by the barrier above). Commit even when empty to keep
        // group numbering exact.
        const int pf = t + 2;
        if (pf < NCHUNK) {
            prefetchB(pf, pf % 3);
            if (pf % 3 == 0) prefetchA(pf / 3, (pf / 3) & 1);
        }
        asm volatile("cp.async.commit_group;" ::: "memory");

        const uint32_t Ab = smem_u32(Abuf[s & 1]);
        const uint32_t Bb = smem_u32(Bbuf[t % 3]);

        // Per-thread fixed row components
        const int rowB0 = wn * 64 + laneB;                 // + nt2*16
        const int rowA0 = wm * 32 + laneA + kx;            // + mt*16

        // B-fragment loader for one ks into bf[which]
        uint32_t bf[2][8][2];
        auto loadB = [&](int ks, int which) {
            #pragma unroll
            for (int nt2 = 0; nt2 < 4; nt2++) {
                int row = rowB0 + nt2 * 16;
                uint32_t addr = Bb + (uint32_t)(row << 7) +
                    (uint32_t)((((ks * 2 + unitB_half) << 4)) ^ ((row & 7) << 4));
                ldsm_x4(bf[which][2 * nt2][0], bf[which][2 * nt2][1],
                        bf[which][2 * nt2 + 1][0], bf[which][2 * nt2 + 1][1], addr);
            }
        };

        loadB(0, 0);
        #pragma unroll
        for (int ks = 0; ks < 4; ks++) {
            const int cur = ks & 1;
            if (ks < 3) loadB(ks + 1, cur ^ 1);   // overlap with HMMAs below
            #pragma unroll
            for (int mt = 0; mt < 2; mt++) {
                int row = rowA0 + mt * 16;
                uint32_t addr = Ab + (uint32_t)(row << 7) +
                    (uint32_t)((((ks * 2 + unitA_half) << 4)) ^ ((row & 7) << 4));
                uint32_t a0, a1, a2, a3;
                ldsm_x4(a0, a1, a2, a3, addr);
                #pragma unroll
                for (int nt = 0; nt < 8; nt++)
                    mma16816(acc[mt][nt], a0, a1, a2, a3,
                             bf[cur][nt][0], bf[cur][nt][1]);
            }
        }
    }

    // ---- epilogue: direct STG.32 stores (each 8-lane g-group = 32B sector) ----
    #pragma unroll
    for (int mt = 0; mt < 2; mt++) {
        const int p0 = wm * 32 + mt * 16 + g;
        #pragma unroll
        for (int nt = 0; nt < 8; nt++) {
            const int n0 = wn * 64 + nt * 8 + 2 * t4;
            const float bv0 = sbias[n0];
            const float bv1 = sbias[n0 + 1];
            float* o0 = out + (((size_t)b * COUT_ + n0) * H_ + y) * W_;
            float* o1 = o0 + (size_t)HW_;     // n0+1
            o0[p0]     = acc[mt][nt][0] + bv0;
            o1[p0]     = acc[mt][nt][1] + bv1;
            o0[p0 + 8] = acc[mt][nt][2] + bv0;
            o1[p0 + 8] = acc[mt][nt][3] + bv1;
        }
    }
}

// ---------------------------------------------------------------------------
extern "C" void kernel_launch(void* const* d_in, const int* in_sizes, int n_in,
                              void* d_out, int out_size) {
    const float* x  = (const float*)d_in[0];   // [32,128,128,128]
    const float* w  = (const float*)d_in[1];   // [128,64,3,3]
    const float* bv = (const float*)d_in[2];   // [128]
    float* out = (float*)d_out;

    static bool attr_set = false;
    if (!attr_set) {
        cudaFuncSetAttribute(conv_mma_kernel,
                             cudaFuncAttributeMaxDynamicSharedMemorySize, SMEM_TOTAL);
        attr_set = true;
    }

    chsum_kernel<<<B_ * C_, 256>>>(x);
    select_wprep_kernel<<<B_ + (NCHUNK * COUT_ * 64 + 255) / 256, 256>>>(w);
    gather_split_kernel<<<dim3(H_, B_), 256>>>(x);
    conv_mma_kernel<<<dim3(H_, B_), 256, SMEM_TOTAL>>>(bv, out);
}